// round 4
// baseline (speedup 1.0000x reference)
#include <cuda_runtime.h>
#include <cuda_bf16.h>
#include <cstdint>

#define HIDDEN      512
#define NUM_LAYERS  8
#define BATCH       16384
#define NUM_OUTPUTS 16

// ---------------- device scratch (allocation-free rule) ----------------
__device__ __nv_bfloat16 g_whi[NUM_LAYERS * HIDDEN * HIDDEN];  // 4 MB
__device__ __nv_bfloat16 g_wlo[NUM_LAYERS * HIDDEN * HIDDEN];  // 4 MB
__device__ __nv_bfloat16 g_ahi[2][BATCH * HIDDEN];             // 2x16 MB
__device__ __nv_bfloat16 g_alo[2][BATCH * HIDDEN];             // 2x16 MB

// ---------------- helpers ----------------
__device__ __forceinline__ uint32_t smem_u32(const void* p) {
    return (uint32_t)__cvta_generic_to_shared(p);
}

#define CP_ASYNC16(dst, src) \
    asm volatile("cp.async.cg.shared.global [%0], [%1], 16;" :: "r"(dst), "l"(src))
#define CP_COMMIT() asm volatile("cp.async.commit_group;" ::: "memory")

#define LDSM_X4(r, addr)                                                        \
    asm volatile("ldmatrix.sync.aligned.m8n8.x4.shared.b16 {%0,%1,%2,%3}, [%4];"\
        : "=r"((r)[0]), "=r"((r)[1]), "=r"((r)[2]), "=r"((r)[3]) : "r"(addr))
#define LDSM_X2(r, addr)                                                        \
    asm volatile("ldmatrix.sync.aligned.m8n8.x2.shared.b16 {%0,%1}, [%2];"      \
        : "=r"((r)[0]), "=r"((r)[1]) : "r"(addr))

#define MMA16816(d, a, b)                                                       \
    asm volatile("mma.sync.aligned.m16n8k16.row.col.f32.bf16.bf16.f32 "         \
        "{%0,%1,%2,%3},{%4,%5,%6,%7},{%8,%9},{%0,%1,%2,%3};"                    \
        : "+f"((d)[0]), "+f"((d)[1]), "+f"((d)[2]), "+f"((d)[3])                \
        : "r"((a)[0]), "r"((a)[1]), "r"((a)[2]), "r"((a)[3]),                   \
          "r"((b)[0]), "r"((b)[1]))

__device__ __forceinline__ uint32_t pk2(float a, float b) {
    __nv_bfloat162 t = __floats2bfloat162_rn(a, b);
    return *reinterpret_cast<uint32_t*>(&t);
}
__device__ __forceinline__ void split_pack(float a, float b, uint32_t& hp, uint32_t& lp) {
    __nv_bfloat16 ha = __float2bfloat16_rn(a);
    __nv_bfloat16 hb = __float2bfloat16_rn(b);
    __nv_bfloat162 H = __halves2bfloat162(ha, hb);
    hp = *reinterpret_cast<uint32_t*>(&H);
    lp = pk2(a - __bfloat162float(ha), b - __bfloat162float(hb));
}

// XOR swizzle: 64B rows of 4x16B quads; q ^= (r>>1)&3 -> 8 consecutive rows
// land in 8 distinct 16B bank groups for ldmatrix.
__device__ __forceinline__ uint32_t swz(int r, int q) {
    return (uint32_t)(r * 64 + ((q ^ ((r >> 1) & 3)) << 4));
}

// ---------------- weight prep: split W*wscale into bf16 hi/lo ----------------
__global__ void wprep_kernel(const float* __restrict__ w,
                             __nv_bfloat16* __restrict__ whi,
                             __nv_bfloat16* __restrict__ wlo) {
    size_t base = ((size_t)blockIdx.x * 256 + threadIdx.x) * 4;
    const float ws = 4.4194173824159216e-4f;  // 0.01 / sqrt(512)
    float4 v = *(const float4*)(w + base);
    uint2 H, L;
    split_pack(v.x * ws, v.y * ws, H.x, L.x);
    split_pack(v.z * ws, v.w * ws, H.y, L.y);
    *(uint2*)(whi + base) = H;
    *(uint2*)(wlo + base) = L;
}

// ---------------- pixel norm -> bf16 hi/lo ----------------
__global__ void pixnorm_kernel(const float* __restrict__ z,
                               __nv_bfloat16* __restrict__ ohi,
                               __nv_bfloat16* __restrict__ olo) {
    int row  = blockIdx.x * 8 + threadIdx.y;
    int lane = threadIdx.x;
    const float4* zr = (const float4*)(z + (size_t)row * HIDDEN);
    float4 v[4];
    float ss = 0.f;
#pragma unroll
    for (int i = 0; i < 4; i++) {
        v[i] = zr[lane + 32 * i];
        ss += v[i].x * v[i].x + v[i].y * v[i].y + v[i].z * v[i].z + v[i].w * v[i].w;
    }
#pragma unroll
    for (int o = 16; o > 0; o >>= 1) ss += __shfl_xor_sync(0xffffffff, ss, o);
    float s = rsqrtf(ss * (1.0f / 512.0f) + 1e-8f);
#pragma unroll
    for (int i = 0; i < 4; i++) {
        float4 t = v[i];
        t.x *= s; t.y *= s; t.z *= s; t.w *= s;
        uint2 H, L;
        split_pack(t.x, t.y, H.x, L.x);
        split_pack(t.z, t.w, H.y, L.y);
        size_t off = (size_t)row * HIDDEN + 4 * (lane + 32 * i);
        *(uint2*)(ohi + off) = H;
        *(uint2*)(olo + off) = L;
    }
}

// ---------------- HMMA GEMM + bias + lrelu (+ fused bcast on last) ----------
// CTA 128(M) x 256(N), 8 warps 2(M)x4(N), warp tile 64x64, K chunks of 32,
// 4-stage cp.async pipeline, XOR-swizzled 64B smem rows.
// Stage layout: Ahi[128x64B]=8K | Alo=8K | Bhi[256x64B]=16K | Blo=16K = 48KB.
#define A_HI_OFF 0
#define A_LO_OFF 8192
#define B_HI_OFF 16384
#define B_LO_OFF 32768
#define STAGE_B  49152
#define NSTAGES  4
#define SMEM_BYTES (NSTAGES * STAGE_B)   // 196608

__global__ __launch_bounds__(256, 1) void gemm_mma_kernel(
    const __nv_bfloat16* __restrict__ Ahi, const __nv_bfloat16* __restrict__ Alo,
    const __nv_bfloat16* __restrict__ Whi, const __nv_bfloat16* __restrict__ Wlo,
    const float* __restrict__ bias,
    __nv_bfloat16* __restrict__ Ohi, __nv_bfloat16* __restrict__ Olo,
    float* __restrict__ outF, int last)
{
    extern __shared__ char smem[];
    const uint32_t sb = smem_u32(smem);
    const int tid  = threadIdx.x;
    const int lane = tid & 31;
    const int warp = tid >> 5;
    const int wm = warp >> 2;       // 0..1
    const int wn = warp & 3;        // 0..3
    const int m0 = blockIdx.y * 128;
    const int n0 = blockIdx.x * 256;

    float acc[4][8][4];
#pragma unroll
    for (int i = 0; i < 4; i++)
#pragma unroll
        for (int j = 0; j < 8; j++)
#pragma unroll
            for (int k = 0; k < 4; k++) acc[i][j][k] = 0.f;

    // ---- async loader: chunk c -> stage s. 3072 x 16B = 48KB ----
    auto load_chunk = [&](int c, int s) {
        const int k0 = c * 32;
        const uint32_t stb = sb + s * STAGE_B;
#pragma unroll
        for (int it = 0; it < 12; it++) {
            int o = it * 256 + tid;   // it0-1:Ahi it2-3:Alo it4-7:Bhi it8-11:Blo
            const __nv_bfloat16* src;
            uint32_t pbase;
            int idx;
            if (o < 512)       { src = Ahi; pbase = A_HI_OFF; idx = o; }
            else if (o < 1024) { src = Alo; pbase = A_LO_OFF; idx = o - 512; }
            else if (o < 2048) { src = Whi; pbase = B_HI_OFF; idx = o - 1024; }
            else               { src = Wlo; pbase = B_LO_OFF; idx = o - 2048; }
            int r = idx >> 2, q = idx & 3;
            int grow = (o < 1024) ? (m0 + r) : (n0 + r);
            CP_ASYNC16(stb + pbase + swz(r, q),
                       src + (size_t)grow * HIDDEN + k0 + q * 8);
        }
        CP_COMMIT();
    };

    load_chunk(0, 0);
    load_chunk(1, 1);
    load_chunk(2, 2);

    const int a_row = lane & 15;
    const int a_kh  = lane >> 4;
    const int b_row = lane & 7;
    const int b_kh  = (lane >> 3) & 1;

    for (int c = 0; c < 16; c++) {
        asm volatile("cp.async.wait_group 2;" ::: "memory");
        __syncthreads();
        if (c + 3 < 16) load_chunk(c + 3, (c + 3) & 3);

        const uint32_t st = sb + (c & 3) * STAGE_B;
#pragma unroll
        for (int ks = 0; ks < 2; ks++) {
            const int qa = ks * 2 + a_kh;
            const int qb = ks * 2 + b_kh;
            uint32_t bhi[8][2], blo_[8][2];
#pragma unroll
            for (int ni = 0; ni < 8; ni++) {
                int rB = wn * 64 + ni * 8 + b_row;
                uint32_t bd = st + B_HI_OFF + swz(rB, qb);
                LDSM_X2(bhi[ni], bd);
                LDSM_X2(blo_[ni], bd + (B_LO_OFF - B_HI_OFF));
            }
#pragma unroll
            for (int mi = 0; mi < 4; mi++) {
                int rA = wm * 64 + mi * 16 + a_row;
                uint32_t ad = st + A_HI_OFF + swz(rA, qa);
                uint32_t ahi[4], alo_[4];
                LDSM_X4(ahi, ad);
                LDSM_X4(alo_, ad + (A_LO_OFF - A_HI_OFF));
#pragma unroll
                for (int ni = 0; ni < 8; ni++) MMA16816(acc[mi][ni], ahi, bhi[ni]);
#pragma unroll
                for (int ni = 0; ni < 8; ni++) MMA16816(acc[mi][ni], ahi, blo_[ni]);
#pragma unroll
                for (int ni = 0; ni < 8; ni++) MMA16816(acc[mi][ni], alo_, bhi[ni]);
            }
        }
    }

    // ---- epilogue ----
    const float gain = 1.41421356237309515f;
    const int t4r = lane >> 2;
    const int t2c = (lane & 3) * 2;
#pragma unroll
    for (int ni = 0; ni < 8; ni++) {
        const int c0 = n0 + wn * 64 + ni * 8 + t2c;
        float2 b2 = *(const float2*)(bias + c0);
        const float bb0 = b2.x * 0.01f, bb1 = b2.y * 0.01f;
#pragma unroll
        for (int mi = 0; mi < 4; mi++) {
            const int r0 = m0 + wm * 64 + mi * 16 + t4r;
            float v0 = acc[mi][ni][0] + bb0;
            float v1 = acc[mi][ni][1] + bb1;
            float v2 = acc[mi][ni][2] + bb0;
            float v3 = acc[mi][ni][3] + bb1;
            v0 = (v0 > 0.f ? v0 : 0.2f * v0) * gain;
            v1 = (v1 > 0.f ? v1 : 0.2f * v1) * gain;
            v2 = (v2 > 0.f ? v2 : 0.2f * v2) * gain;
            v3 = (v3 > 0.f ? v3 : 0.2f * v3) * gain;
            if (!last) {
                uint32_t h01, l01, h23, l23;
                split_pack(v0, v1, h01, l01);
                split_pack(v2, v3, h23, l23);
                *(uint32_t*)(Ohi + (size_t)r0 * HIDDEN + c0)       = h01;
                *(uint32_t*)(Olo + (size_t)r0 * HIDDEN + c0)       = l01;
                *(uint32_t*)(Ohi + (size_t)(r0 + 8) * HIDDEN + c0) = h23;
                *(uint32_t*)(Olo + (size_t)(r0 + 8) * HIDDEN + c0) = l23;
            } else {
                float2 p01 = make_float2(v0, v1);
                float2 p23 = make_float2(v2, v3);
                float* o0 = outF + (size_t)r0 * NUM_OUTPUTS * HIDDEN + c0;
                float* o1 = outF + (size_t)(r0 + 8) * NUM_OUTPUTS * HIDDEN + c0;
#pragma unroll
                for (int j = 0; j < NUM_OUTPUTS; j++) {
                    *(float2*)(o0 + j * HIDDEN) = p01;
                    *(float2*)(o1 + j * HIDDEN) = p23;
                }
            }
        }
    }
}

// ---------------------------------------------------------------------------
extern "C" void kernel_launch(void* const* d_in, const int* in_sizes, int n_in,
                              void* d_out, int out_size) {
    const float* z    = (const float*)d_in[0];
    const float* w    = (const float*)d_in[1];
    const float* bias = (const float*)d_in[2];
    float* out = (float*)d_out;

    __nv_bfloat16 *whi, *wlo, *ahi, *alo;
    cudaGetSymbolAddress((void**)&whi, g_whi);
    cudaGetSymbolAddress((void**)&wlo, g_wlo);
    cudaGetSymbolAddress((void**)&ahi, g_ahi);
    cudaGetSymbolAddress((void**)&alo, g_alo);

    cudaFuncSetAttribute(gemm_mma_kernel,
                         cudaFuncAttributeMaxDynamicSharedMemorySize, SMEM_BYTES);

    // 1) weight split
    wprep_kernel<<<2048, 256>>>(w, whi, wlo);
    // 2) pixel norm + split
    pixnorm_kernel<<<BATCH / 8, dim3(32, 8)>>>(z, ahi, alo);
    // 3) 8 HMMA layers, ping-pong; last fuses broadcast into epilogue
    for (int l = 0; l < NUM_LAYERS; l++) {
        int pi = l & 1, po = pi ^ 1;
        gemm_mma_kernel<<<dim3(HIDDEN / 256, BATCH / 128), 256, SMEM_BYTES>>>(
            ahi + (size_t)pi * BATCH * HIDDEN, alo + (size_t)pi * BATCH * HIDDEN,
            whi + (size_t)l * HIDDEN * HIDDEN, wlo + (size_t)l * HIDDEN * HIDDEN,
            bias + l * HIDDEN,
            ahi + (size_t)po * BATCH * HIDDEN, alo + (size_t)po * BATCH * HIDDEN,
            out, (l == NUM_LAYERS - 1) ? 1 : 0);
    }
}